// round 11
// baseline (speedup 1.0000x reference)
#include <cuda_runtime.h>
#include <math.h>
#include <stdint.h>

#define C      256
#define RBF    64
#define EPB    64     // edges per block (mma edge kernel)
#define NPB    64     // nodes per block (stage B)
#define N_MAX  50000

// Scratch (no cudaMalloc allowed anywhere).
__device__ float    g_agg[(size_t)N_MAX * C];
__device__ uint32_t g_Wr_e[8 * 32 * 32 * 2];   // frag-permuted tf32 W_dist

typedef unsigned long long u64t;

// ---- packed f32x2 helpers (node kernel, proven R4/R6) ----
__device__ __forceinline__ u64t pack2(float lo, float hi) {
    u64t d; asm("mov.b64 %0, {%1, %2};" : "=l"(d) : "f"(lo), "f"(hi)); return d;
}
__device__ __forceinline__ void unpack2(u64t v, float& lo, float& hi) {
    asm("mov.b64 {%0, %1}, %2;" : "=f"(lo), "=f"(hi) : "l"(v));
}
__device__ __forceinline__ u64t ffma2(u64t a, u64t b, u64t c) {
    u64t d; asm("fma.rn.f32x2 %0, %1, %2, %3;" : "=l"(d) : "l"(a), "l"(b), "l"(c));
    return d;
}

// ---- tf32 mma helpers (R5-proven on this bench target) ----
__device__ __forceinline__ uint32_t f2tf32(float f) {
    uint32_t u; asm("cvt.rna.tf32.f32 %0, %1;" : "=r"(u) : "f"(f)); return u;
}
__device__ __forceinline__ void mma_tf32(float c[4], uint32_t a0, uint32_t a1,
                                         uint32_t a2, uint32_t a3,
                                         uint32_t b0, uint32_t b1) {
    asm("mma.sync.aligned.m16n8k8.row.col.f32.tf32.tf32.f32 "
        "{%0,%1,%2,%3}, {%4,%5,%6,%7}, {%8,%9}, {%0,%1,%2,%3};"
        : "+f"(c[0]), "+f"(c[1]), "+f"(c[2]), "+f"(c[3])
        : "r"(a0), "r"(a1), "r"(a2), "r"(a3), "r"(b0), "r"(b1));
}

// ---------------------------------------------------------------------------
__global__ void zero_agg_kernel(int total4) {
    float4 z = make_float4(0.f, 0.f, 0.f, 0.f);
    float4* p = (float4*)g_agg;
    for (int i = blockIdx.x * blockDim.x + threadIdx.x; i < total4;
         i += gridDim.x * blockDim.x)
        p[i] = z;
}

// Permute W_dist into mma B-fragment order, tf32-rounded (R5 verbatim):
// g_Wr_e[((s*32+lane)*32+f)*2 + j] = tf32(W_dist[(s*8 + lane%4 + 4j)*C + f*8 + lane/4])
__global__ void prep_wr_kernel(const float* __restrict__ W_dist) {
    int i = blockIdx.x * blockDim.x + threadIdx.x;
    if (i < 8 * 32 * 32 * 2) {
        int j    = i & 1;
        int f    = (i >> 1) & 31;
        int lane = (i >> 6) & 31;
        int s    = i >> 11;
        int k = s * 8 + (lane & 3) + 4 * j;
        int n = f * 8 + (lane >> 2);
        g_Wr_e[i] = f2tf32(W_dist[k * C + n]);
    }
}

// ---------------------------------------------------------------------------
// Edge stage, mma.sync tf32, 2-CTA/SM shell.
//   P[64,256] = (cut*ef) @ W_dist  (tf32 in, fp32 accum, acc in registers)
//   epilogue per 128-col half: agg[r] += xj * (P + cut*b_dist), sorted runs.
// smem: A[64][68] u32 (17.4K) | P[64][132] f32 (33.8K) | meta
// ---------------------------------------------------------------------------
#define PSTR        132
#define SM_A_OFF    0
#define SM_P_OFF    (64 * 68 * 4)
#define SM_META_OFF (SM_P_OFF + 64 * PSTR * 4)
#define SM_EDGE_TOT (SM_META_OFF + 3 * 64 * 4)

__global__ __launch_bounds__(256, 2) void edge_mma_kernel(
    const int*   __restrict__ node_z,
    const int*   __restrict__ senders,
    const int*   __restrict__ receivers,
    const float* __restrict__ edge_weight,
    const float* __restrict__ edge_feats,
    const float* __restrict__ embed_table,
    const float* __restrict__ b_dist,
    int E)
{
    extern __shared__ unsigned char smem[];
    uint32_t* A_sh   = (uint32_t*)(smem + SM_A_OFF);      // [64][68]
    float*    P_sh   = (float*)(smem + SM_P_OFF);         // [64][PSTR]
    int*      sp_sh  = (int*)(smem + SM_META_OFF);
    int*      r_sh   = sp_sh + EPB;
    float*    cut_sh = (float*)(r_sh + EPB);

    const int e0  = blockIdx.x * EPB;
    const int tid = threadIdx.x;
    const int ne  = min(EPB, E - e0);

    if (tid < EPB) {
        if (tid < ne) {
            int e = e0 + tid;
            sp_sh[tid] = node_z[senders[e]];
            r_sh[tid]  = receivers[e];
            float w = edge_weight[e];
            float cutv = 0.5f * (cosf(w * 0.62831853071795864769f) + 1.0f); // pi/5
            cut_sh[tid] = (w < 5.0f) ? cutv : 0.0f;
        } else {                      // pad edges contribute exactly zero
            sp_sh[tid]  = 0;
            r_sh[tid]   = receivers[e0 + ne - 1];
            cut_sh[tid] = 0.0f;
        }
    }
    __syncthreads();

    // ---- stage A = tf32(cut * ef), zero-padded rows (R5 verbatim) ----
    {
        const float4* src = (const float4*)(edge_feats + (size_t)e0 * RBF);
        for (int idx = tid; idx < EPB * 16; idx += 256) {
            int row = idx >> 4, j = idx & 15;
            float4 v = (row < ne) ? src[idx] : make_float4(0.f, 0.f, 0.f, 0.f);
            float ct = cut_sh[row];
            uint32_t* dst = &A_sh[row * 68 + 4 * j];
            dst[0] = f2tf32(v.x * ct);
            dst[1] = f2tf32(v.y * ct);
            dst[2] = f2tf32(v.z * ct);
            dst[3] = f2tf32(v.w * ct);
        }
    }
    __syncthreads();

    // ---- mma: 8 warps = 4 edge-tiles(16 rows) x 2 n-halves(128 cols) ----
    const int wid  = tid >> 5, lane = tid & 31;
    const int we   = wid >> 1, wn = wid & 1;
    const int g    = lane >> 2, tig = lane & 3;
    const int me   = we * 16;
    const int n0w  = wn * 128;

    float acc[16][4];
    #pragma unroll
    for (int fi = 0; fi < 16; fi++) {
        acc[fi][0] = 0.f; acc[fi][1] = 0.f; acc[fi][2] = 0.f; acc[fi][3] = 0.f;
    }

    #pragma unroll 1
    for (int s = 0; s < 8; s++) {
        const uint32_t* Ab = &A_sh[(me + g) * 68 + s * 8 + tig];
        uint32_t a0 = Ab[0];
        uint32_t a2 = Ab[4];
        uint32_t a1 = Ab[8 * 68];
        uint32_t a3 = Ab[8 * 68 + 4];

        // 8x LDG.128 -> all 16 B-fragments for this k-step (L1/L2-hot)
        uint32_t b[32];
        const uint4* Bp = (const uint4*)(g_Wr_e +
                            ((size_t)(s * 32 + lane) * 32 + (n0w >> 3)) * 2);
        #pragma unroll
        for (int q = 0; q < 8; q++) {
            uint4 v = Bp[q];
            b[4 * q + 0] = v.x; b[4 * q + 1] = v.y;
            b[4 * q + 2] = v.z; b[4 * q + 3] = v.w;
        }

        #pragma unroll
        for (int fi = 0; fi < 16; fi++)
            mma_tf32(acc[fi], a0, a1, a2, a3, b[2 * fi], b[2 * fi + 1]);
    }

    // ---- epilogue: one 128-column half at a time through smem P ----
    const int eg = tid >> 5;          // 8 epilogue groups x 8 edges
    const int q  = lane;              // 32 channel-quads per half
    for (int h = 0; h < 2; h++) {
        if (wn == h) {                // this warp's acc belongs to half h
            #pragma unroll
            for (int fi = 0; fi < 16; fi++) {
                int col = 8 * fi + 2 * tig;
                *(float2*)&P_sh[(me + g) * PSTR + col] =
                    make_float2(acc[fi][0], acc[fi][1]);
                *(float2*)&P_sh[(me + g + 8) * PSTR + col] =
                    make_float2(acc[fi][2], acc[fi][3]);
            }
        }
        __syncthreads();

        const int gc = h * 128 + q * 4;
        const float4 bd4 = *(const float4*)(b_dist + gc);
        float a0 = 0.f, a1 = 0.f, a2 = 0.f, a3 = 0.f;
        int cur = -1;
        #pragma unroll
        for (int i = 0; i < 8; i++) {
            const int e = eg * 8 + i;
            int r = r_sh[e];
            if (r != cur) {
                if (cur >= 0) {
                    float* dst = &g_agg[(size_t)cur * C + gc];
                    atomicAdd(dst + 0, a0); atomicAdd(dst + 1, a1);
                    atomicAdd(dst + 2, a2); atomicAdd(dst + 3, a3);
                }
                a0 = a1 = a2 = a3 = 0.f;
                cur = r;
            }
            float4 P = *(const float4*)&P_sh[e * PSTR + q * 4];
            float  ct = cut_sh[e];
            float4 xj = *(const float4*)(embed_table + (size_t)sp_sh[e] * C + gc);
            a0 = fmaf(xj.x, fmaf(ct, bd4.x, P.x), a0);
            a1 = fmaf(xj.y, fmaf(ct, bd4.y, P.y), a1);
            a2 = fmaf(xj.z, fmaf(ct, bd4.z, P.z), a2);
            a3 = fmaf(xj.w, fmaf(ct, bd4.w, P.w), a3);
        }
        if (cur >= 0) {
            float* dst = &g_agg[(size_t)cur * C + gc];
            atomicAdd(dst + 0, a0); atomicAdd(dst + 1, a1);
            atomicAdd(dst + 2, a2); atomicAdd(dst + 3, a3);
        }
        __syncthreads();
    }
}

// ---------------------------------------------------------------------------
// Stage B (R6 verbatim, proven): out = concat(node_feats, agg) @ W_comb + b
// ---------------------------------------------------------------------------
__global__ __launch_bounds__(256, 2) void node_kernel(
    const float* __restrict__ node_feats,
    const float* __restrict__ W_comb,
    const float* __restrict__ b_comb,
    float*       __restrict__ out,
    int n_nodes)
{
    __shared__ float x2[64][NPB / 2][2];

    const int n0  = blockIdx.x * NPB;
    const int tid = threadIdx.x;
    const int nn  = min(NPB, n_nodes - n0);

    const int g   = tid >> 6;
    const int t64 = tid & 63;
    const int c4  = t64 * 4;
    const int p0  = g * 8;

    u64t acc2[8][4];
    #pragma unroll
    for (int p = 0; p < 8; p++)
        #pragma unroll
        for (int q = 0; q < 4; q++) acc2[p][q] = 0ull;

    for (int kb = 0; kb < 8; kb++) {
        const float* srcbase = (kb < 4) ? node_feats : g_agg;
        const int    off     = (kb & 3) * 64;

        for (int idx = tid; idx < NPB * 16; idx += 256) {
            int row = idx >> 4, j = idx & 15;
            float4 v = (row < nn)
                ? ((const float4*)(srcbase + (size_t)(n0 + row) * C + off))[j]
                : make_float4(0.f, 0.f, 0.f, 0.f);
            int p = row >> 1, hh = row & 1, k = 4 * j;
            x2[k + 0][p][hh] = v.x;
            x2[k + 1][p][hh] = v.y;
            x2[k + 2][p][hh] = v.z;
            x2[k + 3][p][hh] = v.w;
        }
        __syncthreads();

        const float* Wk = W_comb + (size_t)(kb * 64) * C + c4;
        #pragma unroll 4
        for (int k = 0; k < 64; k++) {
            float4 wv = *(const float4*)(Wk + (size_t)k * C);
            u64t w0 = pack2(wv.x, wv.x);
            u64t w1 = pack2(wv.y, wv.y);
            u64t w2 = pack2(wv.z, wv.z);
            u64t w3 = pack2(wv.w, wv.w);
            #pragma unroll
            for (int p = 0; p < 8; p++) {
                u64t x = *(const u64t*)&x2[k][p0 + p][0];
                acc2[p][0] = ffma2(x, w0, acc2[p][0]);
                acc2[p][1] = ffma2(x, w1, acc2[p][1]);
                acc2[p][2] = ffma2(x, w2, acc2[p][2]);
                acc2[p][3] = ffma2(x, w3, acc2[p][3]);
            }
        }
        __syncthreads();
    }

    const float4 b4 = *(const float4*)(b_comb + c4);
    #pragma unroll
    for (int i = 0; i < 16; i++) {
        const int row = g * 16 + i;
        if (row < nn) {
            const int p = i >> 1, hh = i & 1;
            float lo, hi, v0, v1, v2, v3;
            unpack2(acc2[p][0], lo, hi); v0 = (hh ? hi : lo) + b4.x;
            unpack2(acc2[p][1], lo, hi); v1 = (hh ? hi : lo) + b4.y;
            unpack2(acc2[p][2], lo, hi); v2 = (hh ? hi : lo) + b4.z;
            unpack2(acc2[p][3], lo, hi); v3 = (hh ? hi : lo) + b4.w;
            *(float4*)(out + (size_t)(n0 + row) * C + c4) =
                make_float4(v0, v1, v2, v3);
        }
    }
}

// ---------------------------------------------------------------------------
extern "C" void kernel_launch(void* const* d_in, const int* in_sizes, int n_in,
                              void* d_out, int out_size)
{
    const int*   node_z      = (const int*)  d_in[0];
    const float* node_feats  = (const float*)d_in[1];
    const int*   senders     = (const int*)  d_in[2];
    const int*   receivers   = (const int*)  d_in[3];
    const float* edge_weight = (const float*)d_in[4];
    const float* edge_feats  = (const float*)d_in[5];
    const float* embed_table = (const float*)d_in[6];
    const float* W_dist      = (const float*)d_in[7];
    const float* b_dist      = (const float*)d_in[8];
    const float* W_comb      = (const float*)d_in[9];
    const float* b_comb      = (const float*)d_in[10];
    float* out = (float*)d_out;

    const int n_nodes = in_sizes[0];   // 50000
    const int E       = in_sizes[2];   // 800000

    cudaFuncSetAttribute(edge_mma_kernel,
                         cudaFuncAttributeMaxDynamicSharedMemorySize,
                         SM_EDGE_TOT);

    zero_agg_kernel<<<2048, 256>>>(n_nodes * C / 4);
    prep_wr_kernel<<<64, 256>>>(W_dist);

    edge_mma_kernel<<<(E + EPB - 1) / EPB, 256, SM_EDGE_TOT>>>(
        node_z, senders, receivers, edge_weight, edge_feats,
        embed_table, b_dist, E);

    node_kernel<<<(n_nodes + NPB - 1) / NPB, 256>>>(
        node_feats, W_comb, b_comb, out, n_nodes);
}

// round 12
// speedup vs baseline: 1.5780x; 1.5780x over previous
#include <cuda_runtime.h>
#include <math.h>
#include <stdint.h>

#define C      256
#define RBF    64
#define EPB    32     // edges per block  (4 groups x 8 edges)
#define NPB    32     // nodes per block  (4 groups x 8 nodes)
#define N_MAX  50000

// Scratch (no cudaMalloc allowed anywhere).
__device__ float g_agg[(size_t)N_MAX * C];

typedef unsigned long long u64t;

// ---- packed f32x2 helpers ----
__device__ __forceinline__ u64t pack2(float lo, float hi) {
    u64t d; asm("mov.b64 %0, {%1, %2};" : "=l"(d) : "f"(lo), "f"(hi)); return d;
}
__device__ __forceinline__ void unpack2(u64t v, float& lo, float& hi) {
    asm("mov.b64 {%0, %1}, %2;" : "=f"(lo), "=f"(hi) : "l"(v));
}
__device__ __forceinline__ u64t ffma2(u64t a, u64t b, u64t c) {
    u64t d; asm("fma.rn.f32x2 %0, %1, %2, %3;" : "=l"(d) : "l"(a), "l"(b), "l"(c));
    return d;
}

// ---------------------------------------------------------------------------
__global__ void zero_agg_kernel(int total4) {
    float4 z = make_float4(0.f, 0.f, 0.f, 0.f);
    float4* p = (float4*)g_agg;
    for (int i = blockIdx.x * blockDim.x + threadIdx.x; i < total4;
         i += gridDim.x * blockDim.x)
        p[i] = z;
}

// ---------------------------------------------------------------------------
// Edge stage:  agg[r] += embed[z[sender]] * ((cut*ef) @ W_dist + cut*b)
// 256 threads = 4 groups x 64 threads; group = 8 edges (4 packed pairs),
// thread = 4 consecutive channels.  Per k-step per thread:
//   1 LDG.128 (W row slice, L1-hot) + 4 broadcast LDS.64 + 16 FFMA2.
// acc = 16 u64 (32 regs) -> 3 CTAs/SM for latency hiding.
// ---------------------------------------------------------------------------
__global__ __launch_bounds__(256, 3) void edge_kernel(
    const int*   __restrict__ node_z,
    const int*   __restrict__ senders,
    const int*   __restrict__ receivers,
    const float* __restrict__ edge_weight,
    const float* __restrict__ edge_feats,
    const float* __restrict__ embed_table,
    const float* __restrict__ W_dist,
    const float* __restrict__ b_dist,
    int E)
{
    __shared__ float ef2[EPB / 2][RBF][2];   // 8 KB: y = cut*ef, pair-interleaved
    __shared__ int   sp_sh[EPB];
    __shared__ int   r_sh[EPB];
    __shared__ float cut_sh[EPB];

    const int e0  = blockIdx.x * EPB;
    const int tid = threadIdx.x;
    const int ne  = min(EPB, E - e0);

    if (tid < EPB) {
        if (tid < ne) {
            int e = e0 + tid;
            sp_sh[tid] = node_z[senders[e]];
            r_sh[tid]  = receivers[e];
            float w = edge_weight[e];
            float cutv = 0.5f * (cosf(w * 0.62831853071795864769f) + 1.0f); // pi/5
            cut_sh[tid] = (w < 5.0f) ? cutv : 0.0f;
        } else {                     // pad edges contribute exactly zero
            sp_sh[tid]  = 0;
            r_sh[tid]   = receivers[e0 + ne - 1];
            cut_sh[tid] = 0.0f;
        }
    }
    __syncthreads();

    // stage y = cut*ef, pair-interleaved (pad rows zero): 32 edges x 16 quads
    {
        const float4* src = (const float4*)(edge_feats + (size_t)e0 * RBF);
        for (int idx = tid; idx < EPB * 16; idx += 256) {
            int e = idx >> 4, j = idx & 15;
            float4 v = (e < ne) ? src[idx] : make_float4(0.f, 0.f, 0.f, 0.f);
            float ct = cut_sh[e];
            int p = e >> 1, h = e & 1, k = 4 * j;
            ef2[p][k + 0][h] = v.x * ct;
            ef2[p][k + 1][h] = v.y * ct;
            ef2[p][k + 2][h] = v.z * ct;
            ef2[p][k + 3][h] = v.w * ct;
        }
    }
    __syncthreads();

    const int g   = tid >> 6;          // edge group 0..3  (8 edges each)
    const int t64 = tid & 63;
    const int c4  = t64 * 4;           // 4 consecutive channels
    const int p0  = g * 4;             // this group's 4 edge-pairs

    // ---- GEMM: P[pair][ch] accumulators (16 u64 = 32 regs) ----
    u64t acc2[4][4];
    #pragma unroll
    for (int p = 0; p < 4; p++)
        #pragma unroll
        for (int q = 0; q < 4; q++) acc2[p][q] = 0ull;

    #pragma unroll 4
    for (int k = 0; k < RBF; k++) {
        float4 wv = *(const float4*)(W_dist + (size_t)k * C + c4);  // L1-hot
        u64t w0 = pack2(wv.x, wv.x);
        u64t w1 = pack2(wv.y, wv.y);
        u64t w2 = pack2(wv.z, wv.z);
        u64t w3 = pack2(wv.w, wv.w);
        #pragma unroll
        for (int p = 0; p < 4; p++) {
            u64t y = *(const u64t*)&ef2[p0 + p][k][0];   // broadcast LDS.64
            acc2[p][0] = ffma2(y, w0, acc2[p][0]);
            acc2[p][1] = ffma2(y, w1, acc2[p][1]);
            acc2[p][2] = ffma2(y, w2, acc2[p][2]);
            acc2[p][3] = ffma2(y, w3, acc2[p][3]);
        }
    }

    // ---- epilogue: sorted-run accumulation over this group's 8 edges ----
    const float4 bd4 = *(const float4*)(b_dist + c4);
    float a0 = 0.f, a1 = 0.f, a2 = 0.f, a3 = 0.f;
    int   cur = -1;

    #pragma unroll
    for (int i = 0; i < 8; i++) {
        const int e = g * 8 + i;
        const int p = i >> 1;
        const int h = i & 1;

        float P0, P1, P2, P3;
        {
            float lo, hi;
            unpack2(acc2[p][0], lo, hi); P0 = h ? hi : lo;
            unpack2(acc2[p][1], lo, hi); P1 = h ? hi : lo;
            unpack2(acc2[p][2], lo, hi); P2 = h ? hi : lo;
            unpack2(acc2[p][3], lo, hi); P3 = h ? hi : lo;
        }

        int r = r_sh[e];
        if (r != cur) {
            if (cur >= 0) {
                float* dst = &g_agg[(size_t)cur * C + c4];
                atomicAdd(dst + 0, a0); atomicAdd(dst + 1, a1);
                atomicAdd(dst + 2, a2); atomicAdd(dst + 3, a3);
            }
            a0 = a1 = a2 = a3 = 0.f;
            cur = r;
        }
        float  ct = cut_sh[e];
        float4 xj = *(const float4*)(embed_table + (size_t)sp_sh[e] * C + c4);
        a0 = fmaf(xj.x, fmaf(ct, bd4.x, P0), a0);
        a1 = fmaf(xj.y, fmaf(ct, bd4.y, P1), a1);
        a2 = fmaf(xj.z, fmaf(ct, bd4.z, P2), a2);
        a3 = fmaf(xj.w, fmaf(ct, bd4.w, P3), a3);
    }
    if (cur >= 0) {
        float* dst = &g_agg[(size_t)cur * C + c4];
        atomicAdd(dst + 0, a0); atomicAdd(dst + 1, a1);
        atomicAdd(dst + 2, a2); atomicAdd(dst + 3, a3);
    }
}

// ---------------------------------------------------------------------------
// Stage B: out = concat(node_feats, agg) @ W_comb + b_comb
// Same 4ch x 8-row mapping: per k-step per thread
//   1 LDG.128 (W_comb) + 4 broadcast LDS.64 + 16 FFMA2.  3 CTAs/SM.
// K=512 in 8 tiles of 64, alternating node_feats / g_agg.
// ---------------------------------------------------------------------------
__global__ __launch_bounds__(256, 3) void node_kernel(
    const float* __restrict__ node_feats,
    const float* __restrict__ W_comb,
    const float* __restrict__ b_comb,
    float*       __restrict__ out,
    int n_nodes)
{
    __shared__ float x2[64][NPB / 2][2];   // 8 KB, [k][pair][half]

    const int n0  = blockIdx.x * NPB;
    const int tid = threadIdx.x;
    const int nn  = min(NPB, n_nodes - n0);

    const int g   = tid >> 6;          // node group 0..3 (8 nodes each)
    const int t64 = tid & 63;
    const int c4  = t64 * 4;
    const int p0  = g * 4;

    u64t acc2[4][4];
    #pragma unroll
    for (int p = 0; p < 4; p++)
        #pragma unroll
        for (int q = 0; q < 4; q++) acc2[p][q] = 0ull;

    for (int kb = 0; kb < 8; kb++) {
        const float* srcbase = (kb < 4) ? node_feats : g_agg;
        const int    off     = (kb & 3) * 64;

        for (int idx = tid; idx < NPB * 16; idx += 256) {
            int row = idx >> 4, j = idx & 15;
            float4 v = (row < nn)
                ? ((const float4*)(srcbase + (size_t)(n0 + row) * C + off))[j]
                : make_float4(0.f, 0.f, 0.f, 0.f);
            int p = row >> 1, h = row & 1, k = 4 * j;
            x2[k + 0][p][h] = v.x;
            x2[k + 1][p][h] = v.y;
            x2[k + 2][p][h] = v.z;
            x2[k + 3][p][h] = v.w;
        }
        __syncthreads();

        const float* Wk = W_comb + (size_t)(kb * 64) * C + c4;
        #pragma unroll 4
        for (int k = 0; k < 64; k++) {
            float4 wv = *(const float4*)(Wk + (size_t)k * C);   // coalesced
            u64t w0 = pack2(wv.x, wv.x);
            u64t w1 = pack2(wv.y, wv.y);
            u64t w2 = pack2(wv.z, wv.z);
            u64t w3 = pack2(wv.w, wv.w);
            #pragma unroll
            for (int p = 0; p < 4; p++) {
                u64t x = *(const u64t*)&x2[k][p0 + p][0];   // broadcast LDS.64
                acc2[p][0] = ffma2(x, w0, acc2[p][0]);
                acc2[p][1] = ffma2(x, w1, acc2[p][1]);
                acc2[p][2] = ffma2(x, w2, acc2[p][2]);
                acc2[p][3] = ffma2(x, w3, acc2[p][3]);
            }
        }
        __syncthreads();
    }

    const float4 b4 = *(const float4*)(b_comb + c4);
    #pragma unroll
    for (int i = 0; i < 8; i++) {
        const int row = g * 8 + i;
        if (row < nn) {
            const int p = i >> 1, h = i & 1;
            float lo, hi, v0, v1, v2, v3;
            unpack2(acc2[p][0], lo, hi); v0 = (h ? hi : lo) + b4.x;
            unpack2(acc2[p][1], lo, hi); v1 = (h ? hi : lo) + b4.y;
            unpack2(acc2[p][2], lo, hi); v2 = (h ? hi : lo) + b4.z;
            unpack2(acc2[p][3], lo, hi); v3 = (h ? hi : lo) + b4.w;
            *(float4*)(out + (size_t)(n0 + row) * C + c4) =
                make_float4(v0, v1, v2, v3);                // STG.128
        }
    }
}

// ---------------------------------------------------------------------------
extern "C" void kernel_launch(void* const* d_in, const int* in_sizes, int n_in,
                              void* d_out, int out_size)
{
    const int*   node_z      = (const int*)  d_in[0];
    const float* node_feats  = (const float*)d_in[1];
    const int*   senders     = (const int*)  d_in[2];
    const int*   receivers   = (const int*)  d_in[3];
    const float* edge_weight = (const float*)d_in[4];
    const float* edge_feats  = (const float*)d_in[5];
    const float* embed_table = (const float*)d_in[6];
    const float* W_dist      = (const float*)d_in[7];
    const float* b_dist      = (const float*)d_in[8];
    const float* W_comb      = (const float*)d_in[9];
    const float* b_comb      = (const float*)d_in[10];
    float* out = (float*)d_out;

    const int n_nodes = in_sizes[0];   // 50000
    const int E       = in_sizes[2];   // 800000

    zero_agg_kernel<<<2048, 256>>>(n_nodes * C / 4);

    edge_kernel<<<(E + EPB - 1) / EPB, 256>>>(
        node_z, senders, receivers, edge_weight, edge_feats,
        embed_table, W_dist, b_dist, E);

    node_kernel<<<(n_nodes + NPB - 1) / NPB, 256>>>(
        node_feats, W_comb, b_comb, out, n_nodes);
}